// round 1
// baseline (speedup 1.0000x reference)
#include <cuda_runtime.h>
#include <math.h>

#define BATCH   2
#define SEQLEN  2048
#define DMODEL  768
#define DINNER  1536
#define DSTATE  16
#define DCONV   4
#define DTRANK  48
#define NROWS   (BATCH * SEQLEN)          // 4096
#define XDBL_W  (DTRANK + 2 * DSTATE)     // 80

// ---------------- scratch (device globals: no allocation allowed) ----------
__device__ float g_xz[(size_t)NROWS * 2 * DINNER];   // 50.3 MB  (x | z)
__device__ float g_x[(size_t)NROWS * DINNER];        // 25.2 MB  post-conv silu x (dir space)
__device__ float g_xdbl[(size_t)NROWS * XDBL_W];     // 1.3 MB   [dt(48) | B(16) | C(16)]
__device__ float g_delta[(size_t)NROWS * DINNER];    // 25.2 MB
__device__ float g_y[(size_t)NROWS * DINNER];        // 25.2 MB  summed over directions

// ---------------- utility ---------------------------------------------------
__global__ void zero_kernel(float* __restrict__ p, int n) {
    int i = blockIdx.x * blockDim.x + threadIdx.x;
    if (i < n) p[i] = 0.f;
}

// ---------------- generic SGEMM: C[M,N] = A[M,*] * B[N,*]^T -----------------
// Tiles: 128x128x8, 256 threads, 8x8 per-thread microtile.
// kLen = K handled by this z-slice (kStart = blockIdx.z * kLen).
// mode 0: store   mode 1: softplus(acc + bias[n])   mode 2: atomicAdd
__global__ void __launch_bounds__(256)
sgemm_tn(const float* __restrict__ A, const float* __restrict__ B,
         float* __restrict__ C, const float* __restrict__ bias,
         int M, int N, int lda, int ldb, int ldc, int kLen, int mode)
{
    __shared__ float As[8][128];
    __shared__ float Bs[8][128];

    const int tid = threadIdx.x;
    const int m0 = blockIdx.y * 128;
    const int n0 = blockIdx.x * 128;
    const int kStart = blockIdx.z * kLen;

    const int lrow = tid >> 1;            // 0..127
    const int lcol = (tid & 1) * 4;       // 0 or 4
    const float* Aptr = A + (size_t)(m0 + lrow) * lda + kStart + lcol;
    const bool bvalid = (n0 + lrow) < N;
    const float* Bptr = B + (size_t)(n0 + lrow) * ldb + kStart + lcol;

    const int ty = tid >> 4;              // 0..15
    const int tx = tid & 15;              // 0..15

    float acc[8][8];
#pragma unroll
    for (int i = 0; i < 8; i++)
#pragma unroll
        for (int j = 0; j < 8; j++) acc[i][j] = 0.f;

    for (int k0 = 0; k0 < kLen; k0 += 8) {
        float4 av = *(const float4*)(Aptr + k0);
        float4 bv = make_float4(0.f, 0.f, 0.f, 0.f);
        if (bvalid) bv = *(const float4*)(Bptr + k0);

        As[lcol + 0][lrow] = av.x;
        As[lcol + 1][lrow] = av.y;
        As[lcol + 2][lrow] = av.z;
        As[lcol + 3][lrow] = av.w;
        Bs[lcol + 0][lrow] = bv.x;
        Bs[lcol + 1][lrow] = bv.y;
        Bs[lcol + 2][lrow] = bv.z;
        Bs[lcol + 3][lrow] = bv.w;
        __syncthreads();

#pragma unroll
        for (int k = 0; k < 8; k++) {
            float4 a0 = *(const float4*)(&As[k][ty * 8]);
            float4 a1 = *(const float4*)(&As[k][ty * 8 + 4]);
            float4 b0 = *(const float4*)(&Bs[k][tx * 8]);
            float4 b1 = *(const float4*)(&Bs[k][tx * 8 + 4]);
            float a[8] = {a0.x, a0.y, a0.z, a0.w, a1.x, a1.y, a1.z, a1.w};
            float b[8] = {b0.x, b0.y, b0.z, b0.w, b1.x, b1.y, b1.z, b1.w};
#pragma unroll
            for (int i = 0; i < 8; i++)
#pragma unroll
                for (int j = 0; j < 8; j++) acc[i][j] += a[i] * b[j];
        }
        __syncthreads();
    }

#pragma unroll
    for (int i = 0; i < 8; i++) {
        int gm = m0 + ty * 8 + i;
#pragma unroll
        for (int j = 0; j < 8; j++) {
            int gn = n0 + tx * 8 + j;
            if (gn < N) {
                float v = acc[i][j];
                size_t idx = (size_t)gm * ldc + gn;
                if (mode == 0) {
                    C[idx] = v;
                } else if (mode == 1) {
                    v += bias[gn];
                    C[idx] = (v > 20.f) ? v : log1pf(__expf(v));
                } else {
                    atomicAdd(&C[idx], v);
                }
            }
        }
    }
}

// ---------------- causal depthwise conv (k=4) + silu ------------------------
// dir=0: forward sequence; dir=1: operates in flipped index space.
__global__ void conv_silu_kernel(const float* __restrict__ xz,
                                 const float* __restrict__ w,
                                 const float* __restrict__ bconv,
                                 float* __restrict__ xout, int dir)
{
    int idx = blockIdx.x * blockDim.x + threadIdx.x;
    if (idx >= NROWS * DINNER) return;
    int d = idx % DINNER;
    int l = (idx / DINNER) % SEQLEN;
    int b = idx / (DINNER * SEQLEN);

    float acc = bconv[d];
#pragma unroll
    for (int j = 0; j < DCONV; j++) {
        int li = l - (DCONV - 1) + j;
        if (li >= 0) {
            int ls = dir ? (SEQLEN - 1 - li) : li;
            acc += w[d * DCONV + j] * xz[((size_t)b * SEQLEN + ls) * 2 * DINNER + d];
        }
    }
    float sig = 1.f / (1.f + __expf(-acc));
    xout[idx] = acc * sig;
}

// ---------------- selective scan (sequential over L) ------------------------
// One warp handles 2 channels (b,d), 16 lanes = 16 states each.
// Fused epilogue: y_total = (y_scan + x*Dp) * silu(z), written at original pos.
__global__ void scan_kernel(const float* __restrict__ delta,
                            const float* __restrict__ x,
                            const float* __restrict__ xdbl,
                            const float* __restrict__ xz,
                            const float* __restrict__ A_log,
                            const float* __restrict__ Dp,
                            float* __restrict__ y, int dir)
{
    int gwarp = (blockIdx.x * blockDim.x + threadIdx.x) >> 5;  // 0..1535
    int lane = threadIdx.x & 31;
    int s = lane & 15;
    int half = lane >> 4;
    int b = gwarp / (DINNER / 2);
    int dp = gwarp % (DINNER / 2);
    int d = dp * 2 + half;

    float Acoef = -__expf(A_log[d * DSTATE + s]);
    float Dcoef = Dp[d];
    float h = 0.f;

    const size_t rowbase = (size_t)b * SEQLEN;

    // prefetch l = 0
    float nd = delta[rowbase * DINNER + d];
    float nu = x[rowbase * DINNER + d];
    float nB = xdbl[rowbase * XDBL_W + DTRANK + s];
    float nC = xdbl[rowbase * XDBL_W + DTRANK + DSTATE + s];

    for (int l = 0; l < SEQLEN; l++) {
        float dt = nd, u = nu, Bv = nB, Cv = nC;
        if (l + 1 < SEQLEN) {
            size_t r = rowbase + l + 1;
            nd = delta[r * DINNER + d];
            nu = x[r * DINNER + d];
            nB = xdbl[r * XDBL_W + DTRANK + s];
            nC = xdbl[r * XDBL_W + DTRANK + DSTATE + s];
        }
        float dA = __expf(dt * Acoef);
        h = dA * h + (dt * u) * Bv;
        float yv = h * Cv;
        yv += __shfl_xor_sync(0xffffffffu, yv, 8);
        yv += __shfl_xor_sync(0xffffffffu, yv, 4);
        yv += __shfl_xor_sync(0xffffffffu, yv, 2);
        yv += __shfl_xor_sync(0xffffffffu, yv, 1);
        if (s == 0) {
            int pos = dir ? (SEQLEN - 1 - l) : l;
            size_t rp = rowbase + pos;
            float z = xz[rp * 2 * DINNER + DINNER + d];
            float sz = z / (1.f + __expf(-z));
            float val = (yv + u * Dcoef) * sz;
            if (dir) y[rp * DINNER + d] += val;
            else     y[rp * DINNER + d] = val;
        }
    }
}

// ---------------- launch -----------------------------------------------------
extern "C" void kernel_launch(void* const* d_in, const int* in_sizes, int n_in,
                              void* d_out, int out_size)
{
    const float* hidden = (const float*)d_in[0];   // (2,2048,768)
    const float* W_in   = (const float*)d_in[1];   // (3072,768)
    const float* conv_w = (const float*)d_in[2];   // (1536,1,4)
    const float* conv_b = (const float*)d_in[3];   // (1536)
    const float* W_x    = (const float*)d_in[4];   // (80,1536)
    const float* W_dt   = (const float*)d_in[5];   // (1536,48)
    const float* b_dt   = (const float*)d_in[6];   // (1536)
    const float* A_log  = (const float*)d_in[7];   // (1536,16)
    const float* Dp     = (const float*)d_in[8];   // (1536)
    const float* W_out  = (const float*)d_in[9];   // (768,1536)
    float* out = (float*)d_out;                    // (2,2048,768)

    float *xz, *x, *xdbl, *delta, *y;
    cudaGetSymbolAddress((void**)&xz,    g_xz);
    cudaGetSymbolAddress((void**)&x,     g_x);
    cudaGetSymbolAddress((void**)&xdbl,  g_xdbl);
    cudaGetSymbolAddress((void**)&delta, g_delta);
    cudaGetSymbolAddress((void**)&y,     g_y);

    // 1) xz = u @ W_in^T   (shared by both directions: flip commutes with GEMM)
    sgemm_tn<<<dim3(2 * DINNER / 128, NROWS / 128, 1), 256>>>(
        hidden, W_in, xz, nullptr,
        NROWS, 2 * DINNER, DMODEL, DMODEL, 2 * DINNER, DMODEL, 0);

    for (int dir = 0; dir < 2; dir++) {
        // 2) depthwise conv + silu (in direction-flipped index space for dir=1)
        conv_silu_kernel<<<(NROWS * DINNER + 255) / 256, 256>>>(
            xz, conv_w, conv_b, x, dir);

        // 3) x_dbl = x @ W_x^T  (N=80 -> split-K=8 for parallelism, atomicAdd)
        zero_kernel<<<(NROWS * XDBL_W + 255) / 256, 256>>>(xdbl, NROWS * XDBL_W);
        sgemm_tn<<<dim3(1, NROWS / 128, 8), 256>>>(
            x, W_x, xdbl, nullptr,
            NROWS, XDBL_W, DINNER, DINNER, XDBL_W, DINNER / 8, 2);

        // 4) delta = softplus(dt @ W_dt^T + b_dt)   (dt = x_dbl[:, :48], lda=80)
        sgemm_tn<<<dim3(DINNER / 128, NROWS / 128, 1), 256>>>(
            xdbl, W_dt, delta, b_dt,
            NROWS, DINNER, XDBL_W, DTRANK, DINNER, DTRANK, 1);

        // 5) selective scan + fused epilogue, accumulate into y (fwd writes, rev adds)
        scan_kernel<<<(BATCH * DINNER / 2) * 32 / 64, 64>>>(
            delta, x, xdbl, xz, A_log, Dp, y, dir);
    }

    // 6) out = y_total @ W_out^T  (split-K=2 + atomicAdd; d_out is poisoned -> zero)
    zero_kernel<<<(NROWS * DMODEL + 255) / 256, 256>>>(out, NROWS * DMODEL);
    sgemm_tn<<<dim3(DMODEL / 128, NROWS / 128, 2), 256>>>(
        y, W_out, out, nullptr,
        NROWS, DMODEL, DINNER, DINNER, DMODEL, DINNER / 2, 2);
}

// round 2
// speedup vs baseline: 1.4327x; 1.4327x over previous
#include <cuda_runtime.h>
#include <math.h>

#define BATCH   2
#define SEQLEN  2048
#define DMODEL  768
#define DINNER  1536
#define DSTATE  16
#define DCONV   4
#define DTRANK  48
#define NROWS   (BATCH * SEQLEN)          // 4096
#define XDBL_W  (DTRANK + 2 * DSTATE)     // 80
#define TT      4                          // scan time-tile (prefetch depth)

// ---------------- scratch (device globals: no allocation allowed) ----------
__device__ float g_xz[(size_t)NROWS * 2 * DINNER];          // (x | z)
__device__ float g_x[2][(size_t)NROWS * DINNER];            // post-conv silu x, per dir
__device__ float g_xdbl[2][(size_t)NROWS * XDBL_W];         // [dt|B|C], per dir
__device__ float g_delta[2][(size_t)NROWS * DINNER];        // per dir
__device__ float g_y[2][(size_t)NROWS * DINNER];            // per dir scan output

// ---------------- utility ---------------------------------------------------
__global__ void zero_kernel(float* __restrict__ p, int n) {
    int i = blockIdx.x * blockDim.x + threadIdx.x;
    if (i < n) p[i] = 0.f;
}

// ---------------- generic SGEMM: C[M,N] = (A+A2)[M,*] * B[N,*]^T ------------
// Tiles: 128x128x8, 256 threads, 8x8 per-thread microtile.
// kLen = K handled by this z-slice (kStart = blockIdx.z * kLen).
// mode 0: store   mode 1: softplus(acc + bias[n])   mode 2: atomicAdd
__global__ void __launch_bounds__(256)
sgemm_tn(const float* __restrict__ A, const float* __restrict__ A2,
         const float* __restrict__ B,
         float* __restrict__ C, const float* __restrict__ bias,
         int M, int N, int lda, int ldb, int ldc, int kLen, int mode)
{
    __shared__ float As[8][128];
    __shared__ float Bs[8][128];

    const int tid = threadIdx.x;
    const int m0 = blockIdx.y * 128;
    const int n0 = blockIdx.x * 128;
    const int kStart = blockIdx.z * kLen;

    const int lrow = tid >> 1;            // 0..127
    const int lcol = (tid & 1) * 4;       // 0 or 4
    const size_t aoff = (size_t)(m0 + lrow) * lda + kStart + lcol;
    const float* Aptr = A + aoff;
    const float* A2ptr = A2 ? (A2 + aoff) : nullptr;
    const bool bvalid = (n0 + lrow) < N;
    const float* Bptr = B + (size_t)(n0 + lrow) * ldb + kStart + lcol;

    const int ty = tid >> 4;              // 0..15
    const int tx = tid & 15;              // 0..15

    float acc[8][8];
#pragma unroll
    for (int i = 0; i < 8; i++)
#pragma unroll
        for (int j = 0; j < 8; j++) acc[i][j] = 0.f;

    for (int k0 = 0; k0 < kLen; k0 += 8) {
        float4 av = *(const float4*)(Aptr + k0);
        if (A2ptr) {
            float4 a2 = *(const float4*)(A2ptr + k0);
            av.x += a2.x; av.y += a2.y; av.z += a2.z; av.w += a2.w;
        }
        float4 bv = make_float4(0.f, 0.f, 0.f, 0.f);
        if (bvalid) bv = *(const float4*)(Bptr + k0);

        As[lcol + 0][lrow] = av.x;
        As[lcol + 1][lrow] = av.y;
        As[lcol + 2][lrow] = av.z;
        As[lcol + 3][lrow] = av.w;
        Bs[lcol + 0][lrow] = bv.x;
        Bs[lcol + 1][lrow] = bv.y;
        Bs[lcol + 2][lrow] = bv.z;
        Bs[lcol + 3][lrow] = bv.w;
        __syncthreads();

#pragma unroll
        for (int k = 0; k < 8; k++) {
            float4 a0 = *(const float4*)(&As[k][ty * 8]);
            float4 a1 = *(const float4*)(&As[k][ty * 8 + 4]);
            float4 b0 = *(const float4*)(&Bs[k][tx * 8]);
            float4 b1 = *(const float4*)(&Bs[k][tx * 8 + 4]);
            float a[8] = {a0.x, a0.y, a0.z, a0.w, a1.x, a1.y, a1.z, a1.w};
            float b[8] = {b0.x, b0.y, b0.z, b0.w, b1.x, b1.y, b1.z, b1.w};
#pragma unroll
            for (int i = 0; i < 8; i++)
#pragma unroll
                for (int j = 0; j < 8; j++) acc[i][j] += a[i] * b[j];
        }
        __syncthreads();
    }

#pragma unroll
    for (int i = 0; i < 8; i++) {
        int gm = m0 + ty * 8 + i;
#pragma unroll
        for (int j = 0; j < 8; j++) {
            int gn = n0 + tx * 8 + j;
            if (gn < N) {
                float v = acc[i][j];
                size_t idx = (size_t)gm * ldc + gn;
                if (mode == 0) {
                    C[idx] = v;
                } else if (mode == 1) {
                    v += bias[gn];
                    C[idx] = (v > 20.f) ? v : log1pf(__expf(v));
                } else {
                    atomicAdd(&C[idx], v);
                }
            }
        }
    }
}

// ---------------- causal depthwise conv (k=4) + silu, both dirs -------------
__global__ void conv_silu_kernel(const float* __restrict__ xz,
                                 const float* __restrict__ w,
                                 const float* __restrict__ bconv,
                                 float* __restrict__ x0,
                                 float* __restrict__ x1)
{
    int idx = blockIdx.x * blockDim.x + threadIdx.x;
    if (idx >= NROWS * DINNER) return;
    int dir = blockIdx.y;
    int d = idx % DINNER;
    int l = (idx / DINNER) % SEQLEN;
    int b = idx / (DINNER * SEQLEN);

    float acc = bconv[d];
#pragma unroll
    for (int j = 0; j < DCONV; j++) {
        int li = l - (DCONV - 1) + j;
        if (li >= 0) {
            int ls = dir ? (SEQLEN - 1 - li) : li;
            acc += w[d * DCONV + j] * xz[((size_t)b * SEQLEN + ls) * 2 * DINNER + d];
        }
    }
    float sig = 1.f / (1.f + __expf(-acc));
    float* xout = dir ? x1 : x0;
    xout[idx] = acc * sig;
}

// ---------------- selective scan (both directions in one launch) ------------
// One warp handles 2 channels (b,d) of one direction; 16 lanes = 16 states.
// Software-pipelined in tiles of TT timesteps: all 5 input streams for tile
// t+1 are in flight while tile t computes (hides DRAM/L2 latency, MLP=5*TT).
// Fused epilogue: y_dir = (y_scan + x*Dp) * silu(z), written at original pos.
__global__ void __launch_bounds__(128)
scan_kernel(const float* __restrict__ delta0, const float* __restrict__ delta1,
            const float* __restrict__ x0, const float* __restrict__ x1,
            const float* __restrict__ xdbl0, const float* __restrict__ xdbl1,
            const float* __restrict__ xz,
            const float* __restrict__ A_log,
            const float* __restrict__ Dp,
            float* __restrict__ y0, float* __restrict__ y1)
{
    const int gwarp = (blockIdx.x * blockDim.x + threadIdx.x) >> 5;  // 0..3071
    const int lane = threadIdx.x & 31;
    const int s = lane & 15;
    const int half = lane >> 4;
    const int dir = gwarp >= (BATCH * DINNER / 2);
    const int w = gwarp - dir * (BATCH * DINNER / 2);
    const int b = w / (DINNER / 2);
    const int d = (w % (DINNER / 2)) * 2 + half;

    const float* __restrict__ delta = dir ? delta1 : delta0;
    const float* __restrict__ x     = dir ? x1 : x0;
    const float* __restrict__ xdbl  = dir ? xdbl1 : xdbl0;
    float* __restrict__ y           = dir ? y1 : y0;

    const float Acoef = -__expf(A_log[d * DSTATE + s]);
    const float Dcoef = Dp[d];
    float h = 0.f;
    const size_t rowbase = (size_t)b * SEQLEN;

    float cd[TT], cu[TT], cB[TT], cC[TT], cz[TT];

    // prefetch tile 0
#pragma unroll
    for (int i = 0; i < TT; i++) {
        size_t r = rowbase + i;
        cd[i] = delta[r * DINNER + d];
        cu[i] = x[r * DINNER + d];
        cB[i] = xdbl[r * XDBL_W + DTRANK + s];
        cC[i] = xdbl[r * XDBL_W + DTRANK + DSTATE + s];
        int pos = dir ? (SEQLEN - 1 - i) : i;
        cz[i] = xz[(rowbase + pos) * 2 * DINNER + DINNER + d];
    }

    for (int t0 = 0; t0 < SEQLEN; t0 += TT) {
        float nd[TT], nu[TT], nB[TT], nC[TT], nz[TT];
        if (t0 + TT < SEQLEN) {
#pragma unroll
            for (int i = 0; i < TT; i++) {
                size_t r = rowbase + t0 + TT + i;
                nd[i] = delta[r * DINNER + d];
                nu[i] = x[r * DINNER + d];
                nB[i] = xdbl[r * XDBL_W + DTRANK + s];
                nC[i] = xdbl[r * XDBL_W + DTRANK + DSTATE + s];
                int li = t0 + TT + i;
                int pos = dir ? (SEQLEN - 1 - li) : li;
                nz[i] = xz[(rowbase + pos) * 2 * DINNER + DINNER + d];
            }
        }
#pragma unroll
        for (int i = 0; i < TT; i++) {
            float dt = cd[i], u = cu[i];
            float dA = __expf(dt * Acoef);
            h = dA * h + (dt * u) * cB[i];
            float yv = h * cC[i];
            yv += __shfl_xor_sync(0xffffffffu, yv, 8);
            yv += __shfl_xor_sync(0xffffffffu, yv, 4);
            yv += __shfl_xor_sync(0xffffffffu, yv, 2);
            yv += __shfl_xor_sync(0xffffffffu, yv, 1);
            if (s == 0) {
                int l = t0 + i;
                int pos = dir ? (SEQLEN - 1 - l) : l;
                float z = cz[i];
                float sz = z / (1.f + __expf(-z));
                y[(rowbase + pos) * DINNER + d] = (yv + u * Dcoef) * sz;
            }
        }
#pragma unroll
        for (int i = 0; i < TT; i++) {
            cd[i] = nd[i]; cu[i] = nu[i]; cB[i] = nB[i];
            cC[i] = nC[i]; cz[i] = nz[i];
        }
    }
}

// ---------------- launch -----------------------------------------------------
extern "C" void kernel_launch(void* const* d_in, const int* in_sizes, int n_in,
                              void* d_out, int out_size)
{
    const float* hidden = (const float*)d_in[0];   // (2,2048,768)
    const float* W_in   = (const float*)d_in[1];   // (3072,768)
    const float* conv_w = (const float*)d_in[2];   // (1536,1,4)
    const float* conv_b = (const float*)d_in[3];   // (1536)
    const float* W_x    = (const float*)d_in[4];   // (80,1536)
    const float* W_dt   = (const float*)d_in[5];   // (1536,48)
    const float* b_dt   = (const float*)d_in[6];   // (1536)
    const float* A_log  = (const float*)d_in[7];   // (1536,16)
    const float* Dp     = (const float*)d_in[8];   // (1536)
    const float* W_out  = (const float*)d_in[9];   // (768,1536)
    float* out = (float*)d_out;                    // (2,2048,768)

    float *xz, *xb, *xdblb, *deltab, *yb;
    cudaGetSymbolAddress((void**)&xz,     g_xz);
    cudaGetSymbolAddress((void**)&xb,     g_x);
    cudaGetSymbolAddress((void**)&xdblb,  g_xdbl);
    cudaGetSymbolAddress((void**)&deltab, g_delta);
    cudaGetSymbolAddress((void**)&yb,     g_y);
    float* x0 = xb;                         float* x1 = xb + (size_t)NROWS * DINNER;
    float* xd0 = xdblb;                     float* xd1 = xdblb + (size_t)NROWS * XDBL_W;
    float* dl0 = deltab;                    float* dl1 = deltab + (size_t)NROWS * DINNER;
    float* y0 = yb;                         float* y1 = yb + (size_t)NROWS * DINNER;

    // 1) xz = u @ W_in^T   (shared by both directions: flip commutes with GEMM)
    sgemm_tn<<<dim3(2 * DINNER / 128, NROWS / 128, 1), 256>>>(
        hidden, nullptr, W_in, xz, nullptr,
        NROWS, 2 * DINNER, DMODEL, DMODEL, 2 * DINNER, DMODEL, 0);

    // 2) depthwise conv + silu, both directions in one launch
    conv_silu_kernel<<<dim3((NROWS * DINNER + 255) / 256, 2), 256>>>(
        xz, conv_w, conv_b, x0, x1);

    // 3) x_dbl = x @ W_x^T  (N=80 -> split-K=8 for parallelism, atomicAdd)
    zero_kernel<<<(2 * NROWS * XDBL_W + 255) / 256, 256>>>(xd0, 2 * NROWS * XDBL_W);
    sgemm_tn<<<dim3(1, NROWS / 128, 8), 256>>>(
        x0, nullptr, W_x, xd0, nullptr,
        NROWS, XDBL_W, DINNER, DINNER, XDBL_W, DINNER / 8, 2);
    sgemm_tn<<<dim3(1, NROWS / 128, 8), 256>>>(
        x1, nullptr, W_x, xd1, nullptr,
        NROWS, XDBL_W, DINNER, DINNER, XDBL_W, DINNER / 8, 2);

    // 4) delta = softplus(dt @ W_dt^T + b_dt)   (dt = x_dbl[:, :48], lda=80)
    sgemm_tn<<<dim3(DINNER / 128, NROWS / 128, 1), 256>>>(
        xd0, nullptr, W_dt, dl0, b_dt,
        NROWS, DINNER, XDBL_W, DTRANK, DINNER, DTRANK, 1);
    sgemm_tn<<<dim3(DINNER / 128, NROWS / 128, 1), 256>>>(
        xd1, nullptr, W_dt, dl1, b_dt,
        NROWS, DINNER, XDBL_W, DTRANK, DINNER, DTRANK, 1);

    // 5) merged bidirectional selective scan + fused epilogue
    scan_kernel<<<(2 * BATCH * (DINNER / 2) * 32) / 128, 128>>>(
        dl0, dl1, x0, x1, xd0, xd1, xz, A_log, Dp, y0, y1);

    // 6) out = (y0 + y1) @ W_out^T  (sum fused into A-load; split-K=2 + atomic)
    zero_kernel<<<(NROWS * DMODEL + 255) / 256, 256>>>(out, NROWS * DMODEL);
    sgemm_tn<<<dim3(DMODEL / 128, NROWS / 128, 2), 256>>>(
        y0, y1, W_out, out, nullptr,
        NROWS, DMODEL, DINNER, DINNER, DMODEL, DINNER / 2, 2);
}

// round 3
// speedup vs baseline: 2.3908x; 1.6688x over previous
#include <cuda_runtime.h>
#include <math.h>

#define BATCH   2
#define SEQLEN  2048
#define DMODEL  768
#define DINNER  1536
#define DSTATE  16
#define DCONV   4
#define DTRANK  48
#define NROWS   (BATCH * SEQLEN)          // 4096
#define XDBL_W  (DTRANK + 2 * DSTATE)     // 80
#define TT      4                          // scan time-tile (prefetch depth)
#define NCHUNK  32
#define CLEN    (SEQLEN / NCHUNK)          // 64
#define NCHROW  (2 * BATCH * NCHUNK)       // 128 chunk-rows (dir,b,chunk)
#define CHW     (DINNER * DSTATE)          // 24576 per chunk-row

// ---------------- scratch (device globals: no allocation allowed) ----------
__device__ float g_xz[(size_t)NROWS * 2 * DINNER];          // (x | z)
__device__ float g_x[2][(size_t)NROWS * DINNER];            // post-conv silu x, per dir
__device__ float g_xdbl[2][(size_t)NROWS * XDBL_W];         // [dt|B|C], per dir
__device__ float g_delta[2][(size_t)NROWS * DINNER];        // per dir
__device__ float g_y[2][(size_t)NROWS * DINNER];            // per dir scan output
__device__ float g_q[(size_t)NCHROW * CHW];                 // per-chunk local final h
__device__ float g_hin[(size_t)NCHROW * CHW];               // per-chunk incoming h
__device__ float g_S[(size_t)NCHROW * DINNER];              // per-chunk sum of dt

// ---------------- utility ---------------------------------------------------
__global__ void zero_kernel(float* __restrict__ p, int n) {
    int i = blockIdx.x * blockDim.x + threadIdx.x;
    if (i < n) p[i] = 0.f;
}

// ---------------- generic SGEMM: C[M,N] = (A+Aadd)[M,*] * B[N,*]^T ----------
// Tiles: 128x128x8, 256 threads, 8x8 per-thread microtile.
// blockIdx.z = dir * kSlices + kslice ; A/C selected by dir.
// mode 0: store   mode 1: softplus(acc + bias[n])   mode 2: atomicAdd
__global__ void __launch_bounds__(256)
sgemm_tn(const float* __restrict__ A0, const float* __restrict__ A1,
         const float* __restrict__ Aadd, const float* __restrict__ B,
         float* __restrict__ C0, float* __restrict__ C1,
         const float* __restrict__ bias,
         int M, int N, int lda, int ldb, int ldc, int kLen, int kSlices, int mode)
{
    __shared__ float As[8][128];
    __shared__ float Bs[8][128];

    const int tid = threadIdx.x;
    const int m0 = blockIdx.y * 128;
    const int n0 = blockIdx.x * 128;
    const int dir = blockIdx.z / kSlices;
    const int kStart = (blockIdx.z % kSlices) * kLen;
    const float* A = dir ? A1 : A0;
    float* C = dir ? C1 : C0;

    const int lrow = tid >> 1;            // 0..127
    const int lcol = (tid & 1) * 4;       // 0 or 4
    const size_t aoff = (size_t)(m0 + lrow) * lda + kStart + lcol;
    const float* Aptr = A + aoff;
    const float* A2ptr = Aadd ? (Aadd + aoff) : nullptr;
    const bool bvalid = (n0 + lrow) < N;
    const float* Bptr = B + (size_t)(n0 + lrow) * ldb + kStart + lcol;

    const int ty = tid >> 4;              // 0..15
    const int tx = tid & 15;              // 0..15

    float acc[8][8];
#pragma unroll
    for (int i = 0; i < 8; i++)
#pragma unroll
        for (int j = 0; j < 8; j++) acc[i][j] = 0.f;

    for (int k0 = 0; k0 < kLen; k0 += 8) {
        float4 av = *(const float4*)(Aptr + k0);
        if (A2ptr) {
            float4 a2 = *(const float4*)(A2ptr + k0);
            av.x += a2.x; av.y += a2.y; av.z += a2.z; av.w += a2.w;
        }
        float4 bv = make_float4(0.f, 0.f, 0.f, 0.f);
        if (bvalid) bv = *(const float4*)(Bptr + k0);

        As[lcol + 0][lrow] = av.x;
        As[lcol + 1][lrow] = av.y;
        As[lcol + 2][lrow] = av.z;
        As[lcol + 3][lrow] = av.w;
        Bs[lcol + 0][lrow] = bv.x;
        Bs[lcol + 1][lrow] = bv.y;
        Bs[lcol + 2][lrow] = bv.z;
        Bs[lcol + 3][lrow] = bv.w;
        __syncthreads();

#pragma unroll
        for (int k = 0; k < 8; k++) {
            float4 a0 = *(const float4*)(&As[k][ty * 8]);
            float4 a1 = *(const float4*)(&As[k][ty * 8 + 4]);
            float4 b0 = *(const float4*)(&Bs[k][tx * 8]);
            float4 b1 = *(const float4*)(&Bs[k][tx * 8 + 4]);
            float a[8] = {a0.x, a0.y, a0.z, a0.w, a1.x, a1.y, a1.z, a1.w};
            float b[8] = {b0.x, b0.y, b0.z, b0.w, b1.x, b1.y, b1.z, b1.w};
#pragma unroll
            for (int i = 0; i < 8; i++)
#pragma unroll
                for (int j = 0; j < 8; j++) acc[i][j] += a[i] * b[j];
        }
        __syncthreads();
    }

#pragma unroll
    for (int i = 0; i < 8; i++) {
        int gm = m0 + ty * 8 + i;
#pragma unroll
        for (int j = 0; j < 8; j++) {
            int gn = n0 + tx * 8 + j;
            if (gn < N) {
                float v = acc[i][j];
                size_t idx = (size_t)gm * ldc + gn;
                if (mode == 0) {
                    C[idx] = v;
                } else if (mode == 1) {
                    v += bias[gn];
                    C[idx] = (v > 20.f) ? v : log1pf(__expf(v));
                } else {
                    atomicAdd(&C[idx], v);
                }
            }
        }
    }
}

// ---------------- causal depthwise conv (k=4) + silu, both dirs -------------
__global__ void conv_silu_kernel(const float* __restrict__ xz,
                                 const float* __restrict__ w,
                                 const float* __restrict__ bconv,
                                 float* __restrict__ x0,
                                 float* __restrict__ x1)
{
    int idx = blockIdx.x * blockDim.x + threadIdx.x;
    if (idx >= NROWS * DINNER) return;
    int dir = blockIdx.y;
    int d = idx % DINNER;
    int l = (idx / DINNER) % SEQLEN;
    int b = idx / (DINNER * SEQLEN);

    float acc = bconv[d];
#pragma unroll
    for (int j = 0; j < DCONV; j++) {
        int li = l - (DCONV - 1) + j;
        if (li >= 0) {
            int ls = dir ? (SEQLEN - 1 - li) : li;
            acc += w[d * DCONV + j] * xz[((size_t)b * SEQLEN + ls) * 2 * DINNER + d];
        }
    }
    float sig = 1.f / (1.f + __expf(-acc));
    float* xout = dir ? x1 : x0;
    xout[idx] = acc * sig;
}

// ---------------- warp decomposition shared by scan passes 1 & 3 ------------
// warp -> (dir, b, chunk, dpair); lane -> (half, s). One warp: 2 channels x 16 states.
struct ScanIdx {
    int dir, b, chunk, d, s, row;
    size_t rowbase;   // first seq row (in dir space) of this chunk
};
__device__ __forceinline__ ScanIdx scan_idx(int gwarp, int lane) {
    ScanIdx o;
    o.s = lane & 15;
    int half = lane >> 4;
    int w = gwarp;
    int dpair = w % (DINNER / 2); w /= (DINNER / 2);
    o.chunk = w % NCHUNK; w /= NCHUNK;
    o.b = w & 1;
    o.dir = w >> 1;
    o.d = dpair * 2 + half;
    o.row = (o.dir * 2 + o.b) * NCHUNK + o.chunk;
    o.rowbase = (size_t)o.b * SEQLEN + o.chunk * CLEN;
    return o;
}

// ---------------- scan pass 1: per-chunk local scan (h0 = 0) ----------------
// Emits q[row][d*16+s] = local final h, S[row][d] = sum of dt over chunk.
__global__ void __launch_bounds__(128)
scan_pass1(const float* __restrict__ dl0, const float* __restrict__ dl1,
           const float* __restrict__ x0, const float* __restrict__ x1,
           const float* __restrict__ xd0, const float* __restrict__ xd1,
           const float* __restrict__ A_log,
           float* __restrict__ q, float* __restrict__ Ssum)
{
    const int gwarp = (blockIdx.x * blockDim.x + threadIdx.x) >> 5;
    const int lane = threadIdx.x & 31;
    ScanIdx ix = scan_idx(gwarp, lane);

    const float* __restrict__ delta = ix.dir ? dl1 : dl0;
    const float* __restrict__ x     = ix.dir ? x1 : x0;
    const float* __restrict__ xdbl  = ix.dir ? xd1 : xd0;

    const float Acoef = -__expf(A_log[ix.d * DSTATE + ix.s]);
    float h = 0.f, S = 0.f;

    float cd[TT], cu[TT], cB[TT];
#pragma unroll
    for (int i = 0; i < TT; i++) {
        size_t r = ix.rowbase + i;
        cd[i] = delta[r * DINNER + ix.d];
        cu[i] = x[r * DINNER + ix.d];
        cB[i] = xdbl[r * XDBL_W + DTRANK + ix.s];
    }
    for (int t0 = 0; t0 < CLEN; t0 += TT) {
        float nd[TT], nu[TT], nB[TT];
        if (t0 + TT < CLEN) {
#pragma unroll
            for (int i = 0; i < TT; i++) {
                size_t r = ix.rowbase + t0 + TT + i;
                nd[i] = delta[r * DINNER + ix.d];
                nu[i] = x[r * DINNER + ix.d];
                nB[i] = xdbl[r * XDBL_W + DTRANK + ix.s];
            }
        }
#pragma unroll
        for (int i = 0; i < TT; i++) {
            float dt = cd[i];
            float dA = __expf(dt * Acoef);
            h = dA * h + (dt * cu[i]) * cB[i];
            S += dt;
        }
#pragma unroll
        for (int i = 0; i < TT; i++) { cd[i] = nd[i]; cu[i] = nu[i]; cB[i] = nB[i]; }
    }
    q[(size_t)ix.row * CHW + ix.d * DSTATE + ix.s] = h;
    if (ix.s == 0) Ssum[(size_t)ix.row * DINNER + ix.d] = S;
}

// ---------------- scan pass 2: chain chunk transitions (tiny) ---------------
// h_in(c) = exp(A*S(c-1)) * h_in(c-1) + q(c-1), per (dir,b,d,s) channel.
__global__ void scan_pass2(const float* __restrict__ q,
                           const float* __restrict__ Ssum,
                           const float* __restrict__ A_log,
                           float* __restrict__ hin)
{
    int t = blockIdx.x * blockDim.x + threadIdx.x;   // < 4*CHW = 98304
    int col = t % CHW;                                // d*16+s
    int s = col & 15;
    int d = col >> 4;
    int bd = t / CHW;                                 // dir*2+b
    float A = -__expf(A_log[d * DSTATE + s]);
    float h = 0.f;
    for (int c = 0; c < NCHUNK; c++) {
        int row = bd * NCHUNK + c;
        hin[(size_t)row * CHW + col] = h;
        h = __expf(A * Ssum[(size_t)row * DINNER + d]) * h + q[(size_t)row * CHW + col];
    }
}

// ---------------- scan pass 3: local scan with true h_in + epilogue ---------
__global__ void __launch_bounds__(128)
scan_pass3(const float* __restrict__ dl0, const float* __restrict__ dl1,
           const float* __restrict__ x0, const float* __restrict__ x1,
           const float* __restrict__ xd0, const float* __restrict__ xd1,
           const float* __restrict__ xz,
           const float* __restrict__ A_log, const float* __restrict__ Dp,
           const float* __restrict__ hin,
           float* __restrict__ y0, float* __restrict__ y1)
{
    const int gwarp = (blockIdx.x * blockDim.x + threadIdx.x) >> 5;
    const int lane = threadIdx.x & 31;
    ScanIdx ix = scan_idx(gwarp, lane);

    const float* __restrict__ delta = ix.dir ? dl1 : dl0;
    const float* __restrict__ x     = ix.dir ? x1 : x0;
    const float* __restrict__ xdbl  = ix.dir ? xd1 : xd0;
    float* __restrict__ y           = ix.dir ? y1 : y0;

    const float Acoef = -__expf(A_log[ix.d * DSTATE + ix.s]);
    const float Dcoef = Dp[ix.d];
    float h = hin[(size_t)ix.row * CHW + ix.d * DSTATE + ix.s];
    const int lbase = ix.chunk * CLEN;    // global l (dir space) of chunk start

    float cd[TT], cu[TT], cB[TT], cC[TT], cz[TT];
#pragma unroll
    for (int i = 0; i < TT; i++) {
        size_t r = ix.rowbase + i;
        cd[i] = delta[r * DINNER + ix.d];
        cu[i] = x[r * DINNER + ix.d];
        cB[i] = xdbl[r * XDBL_W + DTRANK + ix.s];
        cC[i] = xdbl[r * XDBL_W + DTRANK + DSTATE + ix.s];
        int pos = ix.dir ? (SEQLEN - 1 - (lbase + i)) : (lbase + i);
        cz[i] = xz[((size_t)ix.b * SEQLEN + pos) * 2 * DINNER + DINNER + ix.d];
    }
    for (int t0 = 0; t0 < CLEN; t0 += TT) {
        float nd[TT], nu[TT], nB[TT], nC[TT], nz[TT];
        if (t0 + TT < CLEN) {
#pragma unroll
            for (int i = 0; i < TT; i++) {
                size_t r = ix.rowbase + t0 + TT + i;
                nd[i] = delta[r * DINNER + ix.d];
                nu[i] = x[r * DINNER + ix.d];
                nB[i] = xdbl[r * XDBL_W + DTRANK + ix.s];
                nC[i] = xdbl[r * XDBL_W + DTRANK + DSTATE + ix.s];
                int li = lbase + t0 + TT + i;
                int pos = ix.dir ? (SEQLEN - 1 - li) : li;
                nz[i] = xz[((size_t)ix.b * SEQLEN + pos) * 2 * DINNER + DINNER + ix.d];
            }
        }
#pragma unroll
        for (int i = 0; i < TT; i++) {
            float dt = cd[i], u = cu[i];
            float dA = __expf(dt * Acoef);
            h = dA * h + (dt * u) * cB[i];
            float yv = h * cC[i];
            yv += __shfl_xor_sync(0xffffffffu, yv, 8);
            yv += __shfl_xor_sync(0xffffffffu, yv, 4);
            yv += __shfl_xor_sync(0xffffffffu, yv, 2);
            yv += __shfl_xor_sync(0xffffffffu, yv, 1);
            if (ix.s == 0) {
                int l = lbase + t0 + i;
                int pos = ix.dir ? (SEQLEN - 1 - l) : l;
                float z = cz[i];
                float sz = z / (1.f + __expf(-z));
                y[((size_t)ix.b * SEQLEN + pos) * DINNER + ix.d] = (yv + u * Dcoef) * sz;
            }
        }
#pragma unroll
        for (int i = 0; i < TT; i++) {
            cd[i] = nd[i]; cu[i] = nu[i]; cB[i] = nB[i];
            cC[i] = nC[i]; cz[i] = nz[i];
        }
    }
}

// ---------------- launch -----------------------------------------------------
extern "C" void kernel_launch(void* const* d_in, const int* in_sizes, int n_in,
                              void* d_out, int out_size)
{
    const float* hidden = (const float*)d_in[0];   // (2,2048,768)
    const float* W_in   = (const float*)d_in[1];   // (3072,768)
    const float* conv_w = (const float*)d_in[2];   // (1536,1,4)
    const float* conv_b = (const float*)d_in[3];   // (1536)
    const float* W_x    = (const float*)d_in[4];   // (80,1536)
    const float* W_dt   = (const float*)d_in[5];   // (1536,48)
    const float* b_dt   = (const float*)d_in[6];   // (1536)
    const float* A_log  = (const float*)d_in[7];   // (1536,16)
    const float* Dp     = (const float*)d_in[8];   // (1536)
    const float* W_out  = (const float*)d_in[9];   // (768,1536)
    float* out = (float*)d_out;                    // (2,2048,768)

    float *xz, *xb, *xdblb, *deltab, *yb, *q, *hin, *S;
    cudaGetSymbolAddress((void**)&xz,     g_xz);
    cudaGetSymbolAddress((void**)&xb,     g_x);
    cudaGetSymbolAddress((void**)&xdblb,  g_xdbl);
    cudaGetSymbolAddress((void**)&deltab, g_delta);
    cudaGetSymbolAddress((void**)&yb,     g_y);
    cudaGetSymbolAddress((void**)&q,      g_q);
    cudaGetSymbolAddress((void**)&hin,    g_hin);
    cudaGetSymbolAddress((void**)&S,      g_S);
    float* x0 = xb;        float* x1 = xb + (size_t)NROWS * DINNER;
    float* xd0 = xdblb;    float* xd1 = xdblb + (size_t)NROWS * XDBL_W;
    float* dl0 = deltab;   float* dl1 = deltab + (size_t)NROWS * DINNER;
    float* y0 = yb;        float* y1 = yb + (size_t)NROWS * DINNER;

    // L1) zero x_dbl accumulators (both dirs)
    zero_kernel<<<(2 * NROWS * XDBL_W + 255) / 256, 256>>>(xd0, 2 * NROWS * XDBL_W);

    // L2) xz = u @ W_in^T (shared by both directions)
    sgemm_tn<<<dim3(2 * DINNER / 128, NROWS / 128, 1), 256>>>(
        hidden, hidden, nullptr, W_in, xz, xz, nullptr,
        NROWS, 2 * DINNER, DMODEL, DMODEL, 2 * DINNER, DMODEL, 1, 0);

    // L3) depthwise conv + silu, both directions
    conv_silu_kernel<<<dim3((NROWS * DINNER + 255) / 256, 2), 256>>>(
        xz, conv_w, conv_b, x0, x1);

    // L4) x_dbl = x @ W_x^T, both dirs in one launch (split-K=8, atomicAdd)
    sgemm_tn<<<dim3(1, NROWS / 128, 16), 256>>>(
        x0, x1, nullptr, W_x, xd0, xd1, nullptr,
        NROWS, XDBL_W, DINNER, DINNER, XDBL_W, DINNER / 8, 8, 2);

    // L5) delta = softplus(dt @ W_dt^T + b_dt), both dirs in one launch
    sgemm_tn<<<dim3(DINNER / 128, NROWS / 128, 2), 256>>>(
        xd0, xd1, nullptr, W_dt, dl0, dl1, b_dt,
        NROWS, DINNER, XDBL_W, DTRANK, DINNER, DTRANK, 1, 1);

    // L6-L8) chunked selective scan (3 passes)
    const int NW = 2 * BATCH * NCHUNK * (DINNER / 2);   // 98304 warps
    scan_pass1<<<NW * 32 / 128, 128>>>(dl0, dl1, x0, x1, xd0, xd1, A_log, q, S);
    scan_pass2<<<(4 * CHW) / 256, 256>>>(q, S, A_log, hin);
    scan_pass3<<<NW * 32 / 128, 128>>>(dl0, dl1, x0, x1, xd0, xd1, xz,
                                       A_log, Dp, hin, y0, y1);

    // L9-L10) out = (y0 + y1) @ W_out^T (sum fused into A-load; split-K=2)
    zero_kernel<<<(NROWS * DMODEL + 255) / 256, 256>>>(out, NROWS * DMODEL);
    sgemm_tn<<<dim3(DMODEL / 128, NROWS / 128, 2), 256>>>(
        y0, y0, y1, W_out, out, out, nullptr,
        NROWS, DMODEL, DINNER, DINNER, DMODEL, DINNER / 2, 2, 2);
}